// round 2
// baseline (speedup 1.0000x reference)
#include <cuda_runtime.h>
#include <math.h>

#define BATCH 64
#define SEQ   1024
#define D2    1024      // 2*NHID (enc feature dim)
#define DCAT  512       // NHID (cat_emb dim)
#define D3    1536      // 3*NHID (W1 row stride)
#define DA    350
#define DA_PAD 352
#define RR    30
#define MLPD  2048
#define KMLP  46080     // R * 3*NHID
#define ROWS  65536     // B*N
#define NEGV  (-1e9f)
#define KSPLIT 8
#define KCHUNK (KMLP / KSPLIT)  // 5760

// -------- scratch (static device globals; no allocation allowed) --------
__device__ float g_catc[BATCH * DA_PAD];             // W1_cat @ cat_emb  [B, 350]
__device__ float g_s1[23068672];                     // 65536 x 352 (padded)
__device__ float g_s2[BATCH * RR * SEQ];             // logits [B, R, N]
__device__ float g_M[BATCH * RR * D2];               // M_enc  [B, R, 1024]
__device__ float g_BM[BATCH * KMLP];                 // [B, 46080]
__device__ float g_part[KSPLIT * MLPD * BATCH];      // split-K partials

// ======================================================================
// K0: cat contribution  catc[b,a] = sum_d W1[a, 1024+d] * cat_emb[b,d]
// ======================================================================
__global__ void k0_catc(const float* __restrict__ W1, const float* __restrict__ cat) {
    int b = blockIdx.x;
    int warp = threadIdx.x >> 5, lane = threadIdx.x & 31;
    const float* cb = cat + b * DCAT;
    for (int a = warp; a < DA; a += 8) {
        const float* w = W1 + (size_t)a * D3 + D2;
        float s = 0.f;
        for (int d = lane; d < DCAT; d += 32) s += w[d] * cb[d];
        #pragma unroll
        for (int o = 16; o; o >>= 1) s += __shfl_xor_sync(0xffffffffu, s, o);
        if (lane == 0) g_catc[b * DA_PAD + a] = s;
    }
}

// ======================================================================
// K1: s1 = tanh(enc @ W1_encT + catc)   M=65536 N=350(pad 384) K=1024
//     tiles 128x64x16, 256 thr, 8x4 regs
// ======================================================================
__global__ void k1_s1(const float* __restrict__ enc, const float* __restrict__ W1) {
    __shared__ float As[16][128];
    __shared__ float Bs[16][64];
    int t = threadIdx.x;
    int m0 = blockIdx.x * 128;
    int n0 = blockIdx.y * 64;
    int ty = t >> 4, tx = t & 15;
    float acc[8][4];
    #pragma unroll
    for (int i = 0; i < 8; i++)
        #pragma unroll
        for (int j = 0; j < 4; j++) acc[i][j] = 0.f;

    for (int k0 = 0; k0 < D2; k0 += 16) {
        #pragma unroll
        for (int l = 0; l < 2; l++) {
            int idx = t + l * 256;
            int row = idx >> 2, kc = (idx & 3) * 4;
            float4 v = *(const float4*)(enc + (size_t)(m0 + row) * D2 + k0 + kc);
            As[kc + 0][row] = v.x; As[kc + 1][row] = v.y;
            As[kc + 2][row] = v.z; As[kc + 3][row] = v.w;
        }
        {
            int n = t >> 2, kc = (t & 3) * 4;
            float4 v = make_float4(0.f, 0.f, 0.f, 0.f);
            if (n0 + n < DA) v = *(const float4*)(W1 + (size_t)(n0 + n) * D3 + k0 + kc);
            Bs[kc + 0][n] = v.x; Bs[kc + 1][n] = v.y;
            Bs[kc + 2][n] = v.z; Bs[kc + 3][n] = v.w;
        }
        __syncthreads();
        #pragma unroll
        for (int k = 0; k < 16; k++) {
            float a[8], bv[4];
            *(float4*)(a)     = *(const float4*)(&As[k][ty * 8]);
            *(float4*)(a + 4) = *(const float4*)(&As[k][ty * 8 + 4]);
            *(float4*)(bv)    = *(const float4*)(&Bs[k][tx * 4]);
            #pragma unroll
            for (int i = 0; i < 8; i++)
                #pragma unroll
                for (int j = 0; j < 4; j++) acc[i][j] += a[i] * bv[j];
        }
        __syncthreads();
    }
    #pragma unroll
    for (int i = 0; i < 8; i++) {
        int m = m0 + ty * 8 + i;
        int b = m >> 10;
        #pragma unroll
        for (int j = 0; j < 4; j++) {
            int n = n0 + tx * 4 + j;
            if (n < DA)
                g_s1[(size_t)m * DA_PAD + n] = tanhf(acc[i][j] + g_catc[b * DA_PAD + n]);
            else if (n < DA_PAD)
                g_s1[(size_t)m * DA_PAD + n] = 0.f;
        }
    }
}

// ======================================================================
// K2: s2 = s1 @ W2T   M=65536 N=30(pad 32) K=352  -> g_s2[b,r,n]
//     tiles 128x32x32, 256 thr, 4x4 regs
// ======================================================================
__global__ void k2_s2(const float* __restrict__ W2) {
    __shared__ float As[32][128];
    __shared__ float Bs[32][32];
    int t = threadIdx.x;
    int m0 = blockIdx.x * 128;
    int ty = t >> 3, tx = t & 7;   // ty:0..31 (m), tx:0..7 (n)
    float acc[4][4];
    #pragma unroll
    for (int i = 0; i < 4; i++)
        #pragma unroll
        for (int j = 0; j < 4; j++) acc[i][j] = 0.f;

    for (int k0 = 0; k0 < DA_PAD; k0 += 32) {
        #pragma unroll
        for (int l = 0; l < 4; l++) {
            int idx = t + l * 256;
            int row = idx >> 3, kc = (idx & 7) * 4;
            float4 v = *(const float4*)(g_s1 + (size_t)(m0 + row) * DA_PAD + k0 + kc);
            As[kc + 0][row] = v.x; As[kc + 1][row] = v.y;
            As[kc + 2][row] = v.z; As[kc + 3][row] = v.w;
        }
        {
            int r = t >> 3, kc = (t & 7) * 4;
            #pragma unroll
            for (int j = 0; j < 4; j++) {
                int k = k0 + kc + j;
                Bs[kc + j][r] = (r < RR && k < DA) ? W2[r * DA + k] : 0.f;
            }
        }
        __syncthreads();
        #pragma unroll
        for (int k = 0; k < 32; k++) {
            float a[4], bv[4];
            *(float4*)a  = *(const float4*)(&As[k][ty * 4]);
            *(float4*)bv = *(const float4*)(&Bs[k][tx * 4]);
            #pragma unroll
            for (int i = 0; i < 4; i++)
                #pragma unroll
                for (int j = 0; j < 4; j++) acc[i][j] += a[i] * bv[j];
        }
        __syncthreads();
    }
    #pragma unroll
    for (int i = 0; i < 4; i++) {
        int m = m0 + ty * 4 + i;
        int b = m >> 10, npos = m & 1023;
        #pragma unroll
        for (int j = 0; j < 4; j++) {
            int r = tx * 4 + j;
            if (r < RR) g_s2[((size_t)b * RR + r) * SEQ + npos] = acc[i][j];
        }
    }
}

// ======================================================================
// K3: masked softmax over n; writes A into d_out A-region
// ======================================================================
__global__ void k3_softmax(const int* __restrict__ len, float* __restrict__ outA) {
    __shared__ float sred[8];
    int br = blockIdx.x;              // b*RR + r
    int b = br / RR;
    int t = threadIdx.x;              // 256
    int lane = t & 31, warp = t >> 5;
    const float* src = g_s2 + (size_t)br * SEQ;
    int L = len[b];

    float4 v = *(const float4*)(src + t * 4);
    float vv[4] = {v.x, v.y, v.z, v.w};
    #pragma unroll
    for (int j = 0; j < 4; j++) if (t * 4 + j >= L) vv[j] = NEGV;

    float mx = fmaxf(fmaxf(vv[0], vv[1]), fmaxf(vv[2], vv[3]));
    #pragma unroll
    for (int o = 16; o; o >>= 1) mx = fmaxf(mx, __shfl_xor_sync(0xffffffffu, mx, o));
    if (lane == 0) sred[warp] = mx;
    __syncthreads();
    mx = sred[0];
    #pragma unroll
    for (int w = 1; w < 8; w++) mx = fmaxf(mx, sred[w]);

    float e[4], s = 0.f;
    #pragma unroll
    for (int j = 0; j < 4; j++) { e[j] = __expf(vv[j] - mx); s += e[j]; }
    #pragma unroll
    for (int o = 16; o; o >>= 1) s += __shfl_xor_sync(0xffffffffu, s, o);
    __syncthreads();
    if (lane == 0) sred[warp] = s;
    __syncthreads();
    s = 0.f;
    #pragma unroll
    for (int w = 0; w < 8; w++) s += sred[w];
    float inv = 1.f / s;

    float4 o4 = make_float4(e[0] * inv, e[1] * inv, e[2] * inv, e[3] * inv);
    *(float4*)(outA + (size_t)br * SEQ + t * 4) = o4;
}

// ======================================================================
// K4: M_enc[b,r,d] = sum_n A[b,r,n] * enc[b,n,d]
//     grid (8 dtiles, 64 b), nchunk=32, 4r x 4d regs
// ======================================================================
__global__ void k4_mgemm(const float* __restrict__ enc, const float* __restrict__ outA) {
    __shared__ float Ash[32][32];    // [n][r]
    __shared__ float Es[32][128];    // [n][d]
    int t = threadIdx.x;
    int dtile = blockIdx.x, b = blockIdx.y;
    int ty = t >> 5, tx = t & 31;    // ty: r-group (0..7), tx: d-group (0..31)
    const float* Ab = outA + (size_t)b * RR * SEQ;
    const float* Eb = enc + (size_t)b * SEQ * D2 + dtile * 128;
    float acc[4][4];
    #pragma unroll
    for (int i = 0; i < 4; i++)
        #pragma unroll
        for (int j = 0; j < 4; j++) acc[i][j] = 0.f;

    for (int n0 = 0; n0 < SEQ; n0 += 32) {
        {
            int r = t >> 3, nc = (t & 7) * 4;
            float4 v = make_float4(0.f, 0.f, 0.f, 0.f);
            if (r < RR) v = *(const float4*)(Ab + (size_t)r * SEQ + n0 + nc);
            Ash[nc + 0][r] = v.x; Ash[nc + 1][r] = v.y;
            Ash[nc + 2][r] = v.z; Ash[nc + 3][r] = v.w;
        }
        #pragma unroll
        for (int l = 0; l < 4; l++) {
            int idx = t + l * 256;
            int n = idx >> 5, dc = (idx & 31) * 4;
            *(float4*)(&Es[n][dc]) = *(const float4*)(Eb + (size_t)(n0 + n) * D2 + dc);
        }
        __syncthreads();
        #pragma unroll
        for (int n = 0; n < 32; n++) {
            float a[4], e[4];
            *(float4*)a = *(const float4*)(&Ash[n][ty * 4]);
            *(float4*)e = *(const float4*)(&Es[n][tx * 4]);
            #pragma unroll
            for (int i = 0; i < 4; i++)
                #pragma unroll
                for (int j = 0; j < 4; j++) acc[i][j] += a[i] * e[j];
        }
        __syncthreads();
    }
    #pragma unroll
    for (int i = 0; i < 4; i++) {
        int r = ty * 4 + i;
        if (r >= RR) continue;
        #pragma unroll
        for (int j = 0; j < 4; j++) {
            int d = dtile * 128 + tx * 4 + j;
            g_M[((size_t)b * RR + r) * D2 + d] = acc[i][j];
        }
    }
}

// ======================================================================
// K5: assemble BM[b, r*1536 + d]:  d<1024 -> M_enc, else cat_emb (exact,
//     because softmax rows sum to 1)
// ======================================================================
__global__ void k5_bm(const float* __restrict__ cat) {
    size_t idx = ((size_t)blockIdx.x * 256 + threadIdx.x) * 4;
    int b = (int)(idx / KMLP);
    int rem = (int)(idx % KMLP);
    int r = rem / D3, d = rem % D3;
    float4 v;
    if (d < D2) v = *(const float4*)(g_M + ((size_t)b * RR + r) * D2 + d);
    else        v = *(const float4*)(cat + (size_t)b * DCAT + (d - D2));
    *(float4*)(g_BM + idx) = v;
}

// ======================================================================
// K6: split-K GEMM  part[ks, j, b] = sum_{k in split} W_mlp[j,k]*BM[b,k]
//     tiles 128x64x16, grid (16 jtiles, 8 ksplits)
// ======================================================================
__global__ void k6_mlp(const float* __restrict__ Wm) {
    __shared__ float Ws[16][128];
    __shared__ float Bms[16][64];
    int t = threadIdx.x;
    int jtile = blockIdx.x, ks = blockIdx.y;
    int ty = t >> 4, tx = t & 15;
    int kbeg = ks * KCHUNK;
    float acc[8][4];
    #pragma unroll
    for (int i = 0; i < 8; i++)
        #pragma unroll
        for (int j = 0; j < 4; j++) acc[i][j] = 0.f;

    for (int kk = 0; kk < KCHUNK; kk += 16) {
        int k0 = kbeg + kk;
        #pragma unroll
        for (int l = 0; l < 2; l++) {
            int idx = t + l * 256;
            int row = idx >> 2, kc = (idx & 3) * 4;
            float4 v = *(const float4*)(Wm + (size_t)(jtile * 128 + row) * KMLP + k0 + kc);
            Ws[kc + 0][row] = v.x; Ws[kc + 1][row] = v.y;
            Ws[kc + 2][row] = v.z; Ws[kc + 3][row] = v.w;
        }
        {
            int bb = t >> 2, kc = (t & 3) * 4;
            float4 v = *(const float4*)(g_BM + (size_t)bb * KMLP + k0 + kc);
            Bms[kc + 0][bb] = v.x; Bms[kc + 1][bb] = v.y;
            Bms[kc + 2][bb] = v.z; Bms[kc + 3][bb] = v.w;
        }
        __syncthreads();
        #pragma unroll
        for (int k = 0; k < 16; k++) {
            float a[8], bv[4];
            *(float4*)(a)     = *(const float4*)(&Ws[k][ty * 8]);
            *(float4*)(a + 4) = *(const float4*)(&Ws[k][ty * 8 + 4]);
            *(float4*)(bv)    = *(const float4*)(&Bms[k][tx * 4]);
            #pragma unroll
            for (int i = 0; i < 8; i++)
                #pragma unroll
                for (int j = 0; j < 4; j++) acc[i][j] += a[i] * bv[j];
        }
        __syncthreads();
    }
    #pragma unroll
    for (int i = 0; i < 8; i++) {
        int j = jtile * 128 + ty * 8 + i;
        #pragma unroll
        for (int jj = 0; jj < 4; jj++) {
            int b = tx * 4 + jj;
            g_part[((size_t)ks * MLPD + j) * BATCH + b] = acc[i][jj];
        }
    }
}

// ======================================================================
// K7: reduce split-K + bias -> d_out[b*2048 + j]
// ======================================================================
__global__ void k7_reduce(const float* __restrict__ bias, float* __restrict__ out) {
    int idx = blockIdx.x * 256 + threadIdx.x;   // 0 .. 131071
    int j = idx >> 6, b = idx & 63;
    float s = bias[j];
    #pragma unroll
    for (int ks = 0; ks < KSPLIT; ks++)
        s += g_part[((size_t)ks * MLPD + j) * BATCH + b];
    out[(size_t)b * MLPD + j] = s;
}

// ======================================================================
extern "C" void kernel_launch(void* const* d_in, const int* in_sizes, int n_in,
                              void* d_out, int out_size) {
    const float* enc = nullptr;
    const int*   len = nullptr;
    const float* cat = nullptr;
    const float* W1 = nullptr;
    const float* W2 = nullptr;
    const float* Wm = nullptr;
    const float* bm = nullptr;
    for (int i = 0; i < n_in; i++) {
        switch (in_sizes[i]) {
            case 67108864: enc = (const float*)d_in[i]; break;   // [64,1024,1024]
            case 64:       len = (const int*)d_in[i];   break;   // lengths
            case 32768:    cat = (const float*)d_in[i]; break;   // [64,1,512]
            case 537600:   W1  = (const float*)d_in[i]; break;   // [350,1536]
            case 10500:    W2  = (const float*)d_in[i]; break;   // [30,350]
            case 94371840: Wm  = (const float*)d_in[i]; break;   // [2048,46080]
            case 2048:     bm  = (const float*)d_in[i]; break;   // bias
            default: break;                                      // batch_size etc.
        }
    }
    float* outf = (float*)d_out;
    float* outO = outf;                 // [64, 2048]
    float* outA = outf + BATCH * MLPD;  // [64, 30, 1024]

    k0_catc   <<<BATCH, 256>>>(W1, cat);
    k1_s1     <<<dim3(ROWS / 128, 6), 256>>>(enc, W1);
    k2_s2     <<<ROWS / 128, 256>>>(W2);
    k3_softmax<<<BATCH * RR, 256>>>(len, outA);
    k4_mgemm  <<<dim3(8, BATCH), 256>>>(enc, outA);
    k5_bm     <<<(BATCH * KMLP) / (256 * 4), 256>>>(cat);
    k6_mlp    <<<dim3(MLPD / 128, KSPLIT), 256>>>(Wm);
    k7_reduce <<<(BATCH * MLPD) / 256, 256>>>(bm, outO);
}